// round 10
// baseline (speedup 1.0000x reference)
#include <cuda_runtime.h>
#include <cstdint>

// Problem dims
#define TT 128
#define BB 256
#define II 512
#define HH 1024
#define VV 128
#define OO 64
#define NG 4096   // 4*H

// Decomposition: 64 CTAs = 2 batch-blocks x 32 unit-blocks (A-dup 32x instead of 64x)
#define NCTA 64
#define BT 128          // batch rows per CTA (M)
#define UT 32           // hidden units per CTA
#define CT 128          // gate cols per CTA (N) = 4 gates x 32 units
#define KC 64           // K chunk
#define NKC (HH/KC)     // 16
#define NTHR 512        // 16 warps: 4x4 grid, 32x32 tile per warp

#define AS_STRIDE 68
#define STAGE_FLOATS ((BT + CT) * AS_STRIDE)   // 256*68 = 17408

#define PS 129          // P table row stride (token-indexed reads: odd -> banks spread)
#define GS 132          // gates row stride

// smem float offsets (2-stage pipeline; gates aliases stage B1)
#define OFF_P   0                         // 128*129 = 16512
#define OFF_C   16512                     // BT*UT = 4096
#define OFF_B0  20608
#define OFF_B1  (OFF_B0 + STAGE_FLOATS)   // 38016
#define OFF_TOK (OFF_B1 + STAGE_FLOATS)   // 55424
#define SMEM_FLOATS (OFF_TOK + 136)       // 222240 B
#define OFF_G   OFF_B1                    // gates alias (B1 dead at epilogue)

// ---- static scratch ----
__device__ float g_h[2*BB*HH];
__device__ float g_w[NG*HH];
__device__ unsigned g_cnt;
__device__ unsigned g_rel;

__device__ __forceinline__ float tf32r(float x) {
    unsigned v; asm("cvt.rna.tf32.f32 %0, %1;" : "=r"(v) : "f"(x));
    return __uint_as_float(v);
}
__device__ __forceinline__ unsigned ld_acq(const unsigned* p) {
    unsigned v; asm volatile("ld.acquire.gpu.u32 %0, [%1];" : "=r"(v) : "l"(p) : "memory");
    return v;
}
__device__ __forceinline__ void grid_sync() {
    __syncthreads();
    if (threadIdx.x == 0) {
        unsigned r0 = ld_acq(&g_rel);
        __threadfence();
        unsigned old = atomicAdd(&g_cnt, 1u);
        if (old == (unsigned)(NCTA - 1)) {
            g_cnt = 0; __threadfence(); atomicAdd(&g_rel, 1u);
        } else {
            while (ld_acq(&g_rel) == r0) { }
        }
    }
    __syncthreads();
}
__device__ __forceinline__ int colIdx(int j, int unit0) {
    return ((j >> 5) << 10) + unit0 + (j & 31);   // gate*1024 + unit
}
__device__ __forceinline__ void mma8(float d[4], const unsigned a[4], const unsigned b[2]) {
    asm volatile(
        "mma.sync.aligned.m16n8k8.row.col.f32.tf32.tf32.f32 "
        "{%0,%1,%2,%3}, {%4,%5,%6,%7}, {%8,%9}, {%0,%1,%2,%3};\n"
        : "+f"(d[0]), "+f"(d[1]), "+f"(d[2]), "+f"(d[3])
        : "r"(a[0]), "r"(a[1]), "r"(a[2]), "r"(a[3]), "r"(b[0]), "r"(b[1]));
}
__device__ __forceinline__ void cpa16(unsigned dst, const float* src) {
    asm volatile("cp.async.cg.shared.global [%0], [%1], 16;" :: "r"(dst), "l"(src));
}
#define CP_COMMIT() asm volatile("cp.async.commit_group;" ::: "memory")
template<int N> __device__ __forceinline__ void cp_wait() {
    asm volatile("cp.async.wait_group %0;" :: "n"(N) : "memory");
}

// Synchronous tile load with tf32 rounding (P-table phase only).
__device__ __forceinline__ void load_tiles_cvt(
    float* As, float* Ws,
    const float* __restrict__ A, int lda,
    const float* __restrict__ W, int ldw,
    int kc, int unit0, int tid)
{
#pragma unroll
    for (int i = 0; i < 4; i++) {               // A: 2048 float4 / 512 thr
        int id = tid + NTHR * i;
        int r = id >> 4, q = id & 15;
        float4 v = __ldcg((const float4*)(A + (size_t)r * lda + kc + q * 4));
        v.x = tf32r(v.x); v.y = tf32r(v.y); v.z = tf32r(v.z); v.w = tf32r(v.w);
        *(float4*)(As + r * AS_STRIDE + q * 4) = v;
    }
#pragma unroll
    for (int i = 0; i < 4; i++) {               // W: 2048 float4 / 512 thr
        int id = tid + NTHR * i;
        int r = id >> 4, q = id & 15;
        float4 v = __ldcg((const float4*)(W + (size_t)colIdx(r, unit0) * ldw + kc + q * 4));
        v.x = tf32r(v.x); v.y = tf32r(v.y); v.z = tf32r(v.z); v.w = tf32r(v.w);
        *(float4*)(Ws + r * AS_STRIDE + q * 4) = v;
    }
}

// 4x4 warp grid: each warp computes a 32x32 output tile, full K.
__device__ __forceinline__ void mma_chunk(
    const float* As, const float* Ws, float acc[2][4][4],
    int warp_m, int warp_n, int lane)
{
    int lg = lane >> 2, lt = lane & 3;
#pragma unroll
    for (int kk = 0; kk < KC; kk += 8) {
        unsigned a[2][4], b[4][2];
#pragma unroll
        for (int mb = 0; mb < 2; mb++) {
            int r0 = warp_m * 32 + mb * 16 + lg;
            const float* base = As + r0 * AS_STRIDE + kk + lt;
            a[mb][0] = __float_as_uint(base[0]);
            a[mb][1] = __float_as_uint(base[8 * AS_STRIDE]);
            a[mb][2] = __float_as_uint(base[4]);
            a[mb][3] = __float_as_uint(base[8 * AS_STRIDE + 4]);
        }
#pragma unroll
        for (int nb = 0; nb < 4; nb++) {
            int c0 = warp_n * 32 + nb * 8 + lg;
            const float* base = Ws + c0 * AS_STRIDE + kk + lt;
            b[nb][0] = __float_as_uint(base[0]);
            b[nb][1] = __float_as_uint(base[4]);
        }
#pragma unroll
        for (int mb = 0; mb < 2; mb++)
#pragma unroll
            for (int nb = 0; nb < 4; nb++)
                mma8(acc[mb][nb], a[mb], b[nb]);
    }
}

__global__ void __launch_bounds__(NTHR, 1)
lstm_persistent_kernel(
    const void* __restrict__ inp_raw,
    const float* __restrict__ h0,
    const float* __restrict__ c0,
    const float* __restrict__ emb,
    const float* __restrict__ w_ih,
    const float* __restrict__ w_hh,
    const float* __restrict__ b_ih,
    const float* __restrict__ b_hh,
    const float* __restrict__ w_out,
    const float* __restrict__ b_out,
    float* __restrict__ out)
{
    extern __shared__ float sm[];
    float* Psm   = sm + OFF_P;
    float* gates = sm + OFF_G;
    float* csm   = sm + OFF_C;
    int*   toksm = (int*)(sm + OFF_TOK);

    const int tid  = threadIdx.x;
    const int lane = tid & 31, wid = tid >> 5;
    const int warp_m = wid >> 2, warp_n = wid & 3;   // 4x4
    const int cid = blockIdx.x;
    const int bi = cid >> 5, hi = cid & 31;
    const int b0 = bi * BT;
    const int unit0 = hi * UT;
    const int lg = lane >> 2, lt = lane & 3;

    const unsigned sbase = (unsigned)__cvta_generic_to_shared(sm);
    const int* inp32 = (const int*)inp_raw;
    const long long* inp64 = (const long long*)inp_raw;

    // ---- token dtype detection ----
    if (tid == 0) toksm[128] = 0;
    __syncthreads();
    {
        int f = 0;
        for (int i = tid; i < 128; i += NTHR)
            if (inp32[2 * i + 1] != 0) f = 1;
        if (f) atomicOr(&toksm[128], 1);
    }

    // ---- init: tf32-round w_hh -> g_w; tf32-round h0 -> g_h buf0; c0 -> smem ----
    {
        const float4* src = (const float4*)w_hh;
        float4* dst = (float4*)g_w;
        int base = cid * ((NG * HH / 4) / NCTA);
        for (int i = tid; i < (NG * HH / 4) / NCTA; i += NTHR) {
            float4 v = src[base + i];
            v.x = tf32r(v.x); v.y = tf32r(v.y); v.z = tf32r(v.z); v.w = tf32r(v.w);
            dst[base + i] = v;
        }
        const float4* hs = (const float4*)h0;
        float4* hd = (float4*)g_h;
        int hb = cid * ((BB * HH / 4) / NCTA);
        for (int i = tid; i < (BB * HH / 4) / NCTA; i += NTHR) {
            float4 v = hs[hb + i];
            v.x = tf32r(v.x); v.y = tf32r(v.y); v.z = tf32r(v.z); v.w = tf32r(v.w);
            hd[hb + i] = v;
        }
    }
    for (int p = tid; p < BT * UT; p += NTHR) {
        int b = p >> 5, u = p & 31;
        csm[p] = c0[(size_t)(b0 + b) * HH + unit0 + u];
    }
    grid_sync();
    const int tok_is_32 = toksm[128];

    // ---- per-thread cp.async address precompute ----
    int a_src[4];  unsigned a_dst[4];
    int w_src[4];  unsigned w_dst[4];
#pragma unroll
    for (int i = 0; i < 4; i++) {
        int id = tid + NTHR * i;
        int r = id >> 4, q = id & 15;
        a_src[i] = r * HH + q * 4;
        a_dst[i] = (unsigned)((r * AS_STRIDE + q * 4) * 4);
        w_src[i] = colIdx(r, unit0) * HH + q * 4;
        w_dst[i] = (unsigned)(((BT * AS_STRIDE) + r * AS_STRIDE + q * 4) * 4);
    }
    const unsigned bufb[2] = { sbase + OFF_B0 * 4, sbase + OFF_B1 * 4 };

    // ---- P table: P[v][j] = emb[v] . w_ih[col(j)] + b_ih + b_hh ----
    {
        float* As = sm + OFF_B0;
        float* Ws = As + BT * AS_STRIDE;
        float acc[2][4][4];
#pragma unroll
        for (int mb = 0; mb < 2; mb++)
#pragma unroll
            for (int nb = 0; nb < 4; nb++)
#pragma unroll
                for (int e = 0; e < 4; e++) acc[mb][nb][e] = 0.f;

        for (int kc = 0; kc < II; kc += KC) {
            __syncthreads();
            load_tiles_cvt(As, Ws, emb, II, w_ih, II, kc, unit0, tid);
            __syncthreads();
            mma_chunk(As, Ws, acc, warp_m, warp_n, lane);
        }
        __syncthreads();
#pragma unroll
        for (int mb = 0; mb < 2; mb++) {
            int r0 = warp_m * 32 + mb * 16 + lg;
#pragma unroll
            for (int nb = 0; nb < 4; nb++) {
                int c0c = warp_n * 32 + nb * 8 + (lt << 1);
                int gc0 = colIdx(c0c, unit0), gc1 = colIdx(c0c + 1, unit0);
                float bias0 = b_ih[gc0] + b_hh[gc0];
                float bias1 = b_ih[gc1] + b_hh[gc1];
                Psm[r0 * PS + c0c]           = acc[mb][nb][0] + bias0;
                Psm[r0 * PS + c0c + 1]       = acc[mb][nb][1] + bias1;
                Psm[(r0 + 8) * PS + c0c]     = acc[mb][nb][2] + bias0;
                Psm[(r0 + 8) * PS + c0c + 1] = acc[mb][nb][3] + bias1;
            }
        }
        __syncthreads();
    }

    // ---- issue W chunk 0 for step 0 (uncommitted; commits with A0) ----
#pragma unroll
    for (int i = 0; i < 4; i++) cpa16(bufb[0] + w_dst[i], g_w + w_src[i]);

    // ---- recurrence: 2-stage pipeline, SAFE order: wait -> bar -> issue -> mma ----
    for (int t = 0; t < TT; t++) {
        const float* Ag = g_h + (size_t)(t & 1) * (BB * HH) + (size_t)b0 * HH;
        float* Hout = g_h + (size_t)((t + 1) & 1) * (BB * HH);

        if (tid < BT) {
            toksm[tid] = tok_is_32 ? inp32[t * BB + b0 + tid]
                                   : (int)inp64[(size_t)t * BB + b0 + tid];
        }

        float acc[2][4][4];
#pragma unroll
        for (int mb = 0; mb < 2; mb++)
#pragma unroll
            for (int nb = 0; nb < 4; nb++)
#pragma unroll
                for (int e = 0; e < 4; e++) acc[mb][nb][e] = 0.f;

        // A chunk 0 -> B0, commit group {W0, A0}
#pragma unroll
        for (int i = 0; i < 4; i++) cpa16(bufb[0] + a_dst[i], Ag + a_src[i]);
        CP_COMMIT();

        // mainloop: wait(kc) -> bar -> issue(kc+1) -> mma(kc)
        // The barrier guarantees (a) all threads see chunk kc's copied data and
        // (b) all warps finished mma(kc-1) before bufb[1-cur] is overwritten.
#pragma unroll 1
        for (int kc = 0; kc < NKC; kc++) {
            const int cur = kc & 1;
            cp_wait<0>();
            __syncthreads();
            if (kc + 1 < NKC) {
                const int koff = (kc + 1) * KC;
                const unsigned nb_ = bufb[1 - cur];
#pragma unroll
                for (int i = 0; i < 4; i++) cpa16(nb_ + a_dst[i], Ag + a_src[i] + koff);
#pragma unroll
                for (int i = 0; i < 4; i++) cpa16(nb_ + w_dst[i], g_w + w_src[i] + koff);
                CP_COMMIT();
            }
            const float* As = sm + (cur ? OFF_B1 : OFF_B0);
            mma_chunk(As, As + BT * AS_STRIDE, acc, warp_m, warp_n, lane);
        }

        // issue next step's W0 into B0 (uncommitted). B0 last read by mma(14);
        // every warp passed the kc=15 barrier after that.
        const bool last = (t == TT - 1);
        if (!last) {
#pragma unroll
            for (int i = 0; i < 4; i++) cpa16(bufb[0] + w_dst[i], g_w + w_src[i]);
        }
        __syncthreads();   // all warps done mma(15) reads of B1 before gates alias writes

        // epilogue: gates = mma + P[token]  (gates aliases B1)
#pragma unroll
        for (int mb = 0; mb < 2; mb++) {
            int r0 = warp_m * 32 + mb * 16 + lg;
            int v0 = toksm[r0], v1 = toksm[r0 + 8];
#pragma unroll
            for (int nb = 0; nb < 4; nb++) {
                int c0c = warp_n * 32 + nb * 8 + (lt << 1);
                gates[r0 * GS + c0c]           = acc[mb][nb][0] + Psm[v0 * PS + c0c];
                gates[r0 * GS + c0c + 1]       = acc[mb][nb][1] + Psm[v0 * PS + c0c + 1];
                gates[(r0 + 8) * GS + c0c]     = acc[mb][nb][2] + Psm[v1 * PS + c0c];
                gates[(r0 + 8) * GS + c0c + 1] = acc[mb][nb][3] + Psm[v1 * PS + c0c + 1];
            }
        }
        __syncthreads();

        // pointwise LSTM cell (UT=32 units per CTA)
        for (int p = tid; p < BT * UT; p += NTHR) {
            int b = p >> 5, u = p & 31;
            float gi = gates[b * GS + u];
            float gf = gates[b * GS + 32 + u];
            float gg = gates[b * GS + 64 + u];
            float go = gates[b * GS + 96 + u];
            float iv = 1.f / (1.f + expf(-gi));
            float fv = 1.f / (1.f + expf(-gf));
            float gv = tanhf(gg);
            float ov = 1.f / (1.f + expf(-go));
            float cn = fv * csm[p] + iv * gv;
            float hn = ov * tanhf(cn);
            csm[p] = cn;
            Hout[(size_t)(b0 + b) * HH + unit0 + u] = last ? hn : tf32r(hn);
        }
        grid_sync();
    }

    // ---- output head: h_last (fp32) in buffer 0 ----
    if (tid < 256) {
        int id = cid * 256 + tid;            // 64 CTAs x 256 = 16384 = 256*64
        int b = id >> 6, o = id & 63;
        const float4* hr = (const float4*)(g_h + (size_t)b * HH);
        const float4* wr = (const float4*)(w_out + (size_t)o * HH);
        float s = 0.f;
#pragma unroll 8
        for (int k = 0; k < HH / 4; k++) {
            float4 a = __ldcg(hr + k);
            float4 w = wr[k];
            s += a.x * w.x + a.y * w.y + a.z * w.z + a.w * w.w;
        }
        out[id] = s + b_out[o];
    }
}

extern "C" void kernel_launch(void* const* d_in, const int* in_sizes, int n_in,
                              void* d_out, int out_size) {
    (void)in_sizes; (void)n_in; (void)out_size;
    const size_t smem_bytes = (size_t)SMEM_FLOATS * sizeof(float);
    cudaFuncSetAttribute(lstm_persistent_kernel,
                         cudaFuncAttributeMaxDynamicSharedMemorySize, (int)smem_bytes);
    lstm_persistent_kernel<<<NCTA, NTHR, smem_bytes>>>(
        (const void*)d_in[0],
        (const float*)d_in[1],
        (const float*)d_in[2],
        (const float*)d_in[3],
        (const float*)d_in[4],
        (const float*)d_in[5],
        (const float*)d_in[6],
        (const float*)d_in[7],
        (const float*)d_in[8],
        (const float*)d_in[9],
        (float*)d_out);
}

// round 11
// speedup vs baseline: 1.7055x; 1.7055x over previous
#include <cuda_runtime.h>
#include <cstdint>

// Problem dims
#define TT 128
#define BB 256
#define II 512
#define HH 1024
#define VV 128
#define OO 64
#define NG 4096   // 4*H

// Decomposition (R6 champion shape)
#define NCTA 128        // 2 batch-blocks x 64 unit-blocks
#define BT 128          // batch rows per CTA (M)
#define UT 16           // hidden units per CTA
#define CT 64           // gate cols per CTA (N)
#define KC 64           // K chunk
#define NKC (HH/KC)     // 16
#define NTHR 256        // 8 warps: 4x2 warp grid, 32x32 tile per warp

#define AS_STRIDE 68
#define STAGE_FLOATS ((BT + CT) * AS_STRIDE)   // 13056

#define PS 65           // P table row stride (odd -> token-indexed reads conflict-free)

// smem float offsets: P table + tokens + 3 pipeline stages (no gates/c arrays)
#define OFF_P   0                         // 128*65 = 8320 floats
#define OFF_TOK 8320                      // 136 ints
#define OFF_B0  8456
#define OFF_B1  (OFF_B0 + STAGE_FLOATS)   // 21512
#define OFF_B2  (OFF_B1 + STAGE_FLOATS)   // 34568
#define SMEM_FLOATS (OFF_B2 + STAGE_FLOATS)   // 47624 floats = 190496 B

// ---- static scratch ----
__device__ float g_h[2*BB*HH];        // ping-pong hidden state (tf32; fp32 last step)
__device__ float g_w[NG*HH];          // tf32-pre-rounded w_hh
__device__ unsigned g_cnt;
__device__ unsigned g_rel;

__device__ __forceinline__ float tf32r(float x) {
    unsigned v; asm("cvt.rna.tf32.f32 %0, %1;" : "=r"(v) : "f"(x));
    return __uint_as_float(v);
}
__device__ __forceinline__ unsigned ld_acq(const unsigned* p) {
    unsigned v; asm volatile("ld.acquire.gpu.u32 %0, [%1];" : "=r"(v) : "l"(p) : "memory");
    return v;
}
__device__ __forceinline__ void grid_sync() {
    __syncthreads();
    if (threadIdx.x == 0) {
        unsigned r0 = ld_acq(&g_rel);
        __threadfence();
        unsigned old = atomicAdd(&g_cnt, 1u);
        if (old == (unsigned)(NCTA - 1)) {
            g_cnt = 0; __threadfence(); atomicAdd(&g_rel, 1u);
        } else {
            while (ld_acq(&g_rel) == r0) { }
        }
    }
    __syncthreads();
}

// NEW column mapping: local col j -> gate=(j>>3)&3, unit=(j>>5)*8+(j&7).
// Puts all 4 gates of a (row,unit) cell into ONE thread's accumulators.
__device__ __forceinline__ int colIdx(int j, int unit0) {
    return (((j >> 3) & 3) << 10) + unit0 + ((j >> 5) << 3) + (j & 7);
}

__device__ __forceinline__ void mma8(float d[4], const unsigned a[4], const unsigned b[2]) {
    asm volatile(
        "mma.sync.aligned.m16n8k8.row.col.f32.tf32.tf32.f32 "
        "{%0,%1,%2,%3}, {%4,%5,%6,%7}, {%8,%9}, {%0,%1,%2,%3};\n"
        : "+f"(d[0]), "+f"(d[1]), "+f"(d[2]), "+f"(d[3])
        : "r"(a[0]), "r"(a[1]), "r"(a[2]), "r"(a[3]), "r"(b[0]), "r"(b[1]));
}
__device__ __forceinline__ void cpa16(unsigned dst, const float* src) {
    asm volatile("cp.async.cg.shared.global [%0], [%1], 16;" :: "r"(dst), "l"(src));
}
#define CP_COMMIT() asm volatile("cp.async.commit_group;" ::: "memory")
template<int N> __device__ __forceinline__ void cp_wait() {
    asm volatile("cp.async.wait_group %0;" :: "n"(N) : "memory");
}

// fast pointwise ops (error ~2 ulp; negligible vs tf32 2^-11 noise)
__device__ __forceinline__ float fsig(float x) {
    return __fdividef(1.0f, 1.0f + __expf(-x));
}
__device__ __forceinline__ float ftanh(float x) {
    return 1.0f - 2.0f * __fdividef(1.0f, __expf(2.0f * x) + 1.0f);
}

// Synchronous tile load with tf32 rounding (P-table phase only).
__device__ __forceinline__ void load_tiles_cvt(
    float* As, float* Ws,
    const float* __restrict__ A, int lda,
    const float* __restrict__ W, int ldw,
    int kc, int unit0, int tid)
{
#pragma unroll
    for (int i = 0; i < 8; i++) {
        int id = tid + NTHR * i;
        int r = id >> 4, q = id & 15;
        float4 v = __ldcg((const float4*)(A + (size_t)r * lda + kc + q * 4));
        v.x = tf32r(v.x); v.y = tf32r(v.y); v.z = tf32r(v.z); v.w = tf32r(v.w);
        *(float4*)(As + r * AS_STRIDE + q * 4) = v;
    }
#pragma unroll
    for (int i = 0; i < 4; i++) {
        int id = tid + NTHR * i;
        int r = id >> 4, q = id & 15;
        float4 v = __ldcg((const float4*)(W + (size_t)colIdx(r, unit0) * ldw + kc + q * 4));
        v.x = tf32r(v.x); v.y = tf32r(v.y); v.z = tf32r(v.z); v.w = tf32r(v.w);
        *(float4*)(Ws + r * AS_STRIDE + q * 4) = v;
    }
}

// 4x2 warp grid: each warp computes a 32x32 output tile.
__device__ __forceinline__ void mma_chunk(
    const float* As, const float* Ws, float acc[2][4][4],
    int warp_m, int warp_n, int lane)
{
    int lg = lane >> 2, lt = lane & 3;
#pragma unroll
    for (int kk = 0; kk < KC; kk += 8) {
        unsigned a[2][4], b[4][2];
#pragma unroll
        for (int mb = 0; mb < 2; mb++) {
            int r0 = warp_m * 32 + mb * 16 + lg;
            const float* base = As + r0 * AS_STRIDE + kk + lt;
            a[mb][0] = __float_as_uint(base[0]);
            a[mb][1] = __float_as_uint(base[8 * AS_STRIDE]);
            a[mb][2] = __float_as_uint(base[4]);
            a[mb][3] = __float_as_uint(base[8 * AS_STRIDE + 4]);
        }
#pragma unroll
        for (int nb = 0; nb < 4; nb++) {
            int c0 = warp_n * 32 + nb * 8 + lg;
            const float* base = Ws + c0 * AS_STRIDE + kk + lt;
            b[nb][0] = __float_as_uint(base[0]);
            b[nb][1] = __float_as_uint(base[4]);
        }
#pragma unroll
        for (int mb = 0; mb < 2; mb++)
#pragma unroll
            for (int nb = 0; nb < 4; nb++)
                mma8(acc[mb][nb], a[mb], b[nb]);
    }
}

__global__ void __launch_bounds__(NTHR, 1)
lstm_persistent_kernel(
    const void* __restrict__ inp_raw,
    const float* __restrict__ h0,
    const float* __restrict__ c0,
    const float* __restrict__ emb,
    const float* __restrict__ w_ih,
    const float* __restrict__ w_hh,
    const float* __restrict__ b_ih,
    const float* __restrict__ b_hh,
    const float* __restrict__ w_out,
    const float* __restrict__ b_out,
    float* __restrict__ out)
{
    extern __shared__ float sm[];
    float* Psm   = sm + OFF_P;
    int*   toksm = (int*)(sm + OFF_TOK);

    const int tid  = threadIdx.x;
    const int lane = tid & 31, wid = tid >> 5;
    const int warp_m = wid >> 1, warp_n = wid & 1;  // 4x2
    const int cid = blockIdx.x;
    const int bi = cid >> 6, hi = cid & 63;
    const int b0 = bi * BT;
    const int unit0 = hi * UT;
    const int lg = lane >> 2, lt = lane & 3;

    const unsigned sbase = (unsigned)__cvta_generic_to_shared(sm);
    const int* inp32 = (const int*)inp_raw;
    const long long* inp64 = (const long long*)inp_raw;

    // ---- token dtype detection ----
    if (tid == 0) toksm[128] = 0;
    __syncthreads();
    {
        int f = 0;
        for (int i = tid; i < 128; i += NTHR)
            if (inp32[2 * i + 1] != 0) f = 1;
        if (f) atomicOr(&toksm[128], 1);
    }

    // ---- init: tf32-round w_hh -> g_w; tf32-round h0 -> g_h buf0 ----
    {
        const float4* src = (const float4*)w_hh;
        float4* dst = (float4*)g_w;
        int base = cid * ((NG * HH / 4) / NCTA);
        for (int i = tid; i < (NG * HH / 4) / NCTA; i += NTHR) {
            float4 v = src[base + i];
            v.x = tf32r(v.x); v.y = tf32r(v.y); v.z = tf32r(v.z); v.w = tf32r(v.w);
            dst[base + i] = v;
        }
        const float4* hs = (const float4*)h0;
        float4* hd = (float4*)g_h;
        int hb = cid * ((BB * HH / 4) / NCTA);
        for (int i = tid; i < (BB * HH / 4) / NCTA; i += NTHR) {
            float4 v = hs[hb + i];
            v.x = tf32r(v.x); v.y = tf32r(v.y); v.z = tf32r(v.z); v.w = tf32r(v.w);
            hd[hb + i] = v;
        }
    }

    // ---- c state in registers: creg[mb*4 + rh*2 + e] for rows warp_m*32+mb*16+lg+rh*8,
    //      units warp_n*8 + 2lt + e ----
    float creg[8];
    {
        const int u0 = unit0 + warp_n * 8 + (lt << 1);
#pragma unroll
        for (int mb = 0; mb < 2; mb++)
#pragma unroll
            for (int rh = 0; rh < 2; rh++) {
                int r = warp_m * 32 + mb * 16 + rh * 8 + lg;
                const float2 cv = *(const float2*)(c0 + (size_t)(b0 + r) * HH + u0);
                creg[mb * 4 + rh * 2 + 0] = cv.x;
                creg[mb * 4 + rh * 2 + 1] = cv.y;
            }
    }
    grid_sync();
    const int tok_is_32 = toksm[128];

    // ---- per-thread cp.async address precompute ----
    int a_src[8];  unsigned a_dst[8];
    int w_src[4];  unsigned w_dst[4];
#pragma unroll
    for (int i = 0; i < 8; i++) {
        int id = tid + NTHR * i;
        int r = id >> 4, q = id & 15;
        a_src[i] = r * HH + q * 4;
        a_dst[i] = (unsigned)((r * AS_STRIDE + q * 4) * 4);
    }
#pragma unroll
    for (int i = 0; i < 4; i++) {
        int id = tid + NTHR * i;
        int r = id >> 4, q = id & 15;
        w_src[i] = colIdx(r, unit0) * HH + q * 4;
        w_dst[i] = (unsigned)(((BT * AS_STRIDE) + r * AS_STRIDE + q * 4) * 4);
    }
    const unsigned bufb[3] = { sbase + OFF_B0 * 4, sbase + OFF_B1 * 4, sbase + OFF_B2 * 4 };

    // ---- P table: P[v][j] = emb[v] . w_ih[col(j)] + b_ih + b_hh ----
    {
        float* As = sm + OFF_B0;
        float* Ws = As + BT * AS_STRIDE;
        float acc[2][4][4];
#pragma unroll
        for (int mb = 0; mb < 2; mb++)
#pragma unroll
            for (int nb = 0; nb < 4; nb++)
#pragma unroll
                for (int e = 0; e < 4; e++) acc[mb][nb][e] = 0.f;

        for (int kc = 0; kc < II; kc += KC) {
            __syncthreads();
            load_tiles_cvt(As, Ws, emb, II, w_ih, II, kc, unit0, tid);
            __syncthreads();
            mma_chunk(As, Ws, acc, warp_m, warp_n, lane);
        }
        __syncthreads();
#pragma unroll
        for (int mb = 0; mb < 2; mb++) {
            int r0 = warp_m * 32 + mb * 16 + lg;
#pragma unroll
            for (int nb = 0; nb < 4; nb++) {
                int c0c = warp_n * 32 + nb * 8 + (lt << 1);
                int gc0 = colIdx(c0c, unit0), gc1 = colIdx(c0c + 1, unit0);
                float bias0 = b_ih[gc0] + b_hh[gc0];
                float bias1 = b_ih[gc1] + b_hh[gc1];
                Psm[r0 * PS + c0c]           = acc[mb][nb][0] + bias0;
                Psm[r0 * PS + c0c + 1]       = acc[mb][nb][1] + bias1;
                Psm[(r0 + 8) * PS + c0c]     = acc[mb][nb][2] + bias0;
                Psm[(r0 + 8) * PS + c0c + 1] = acc[mb][nb][3] + bias1;
            }
        }
        __syncthreads();
    }

    // ---- issue W chunk 0 for step 0 (uncommitted; commits with A0) ----
#pragma unroll
    for (int i = 0; i < 4; i++) cpa16(bufb[0] + w_dst[i], g_w + w_src[i]);

    // ---- recurrence: 3-stage pipeline (R6 ordering), register epilogue ----
    for (int t = 0; t < TT; t++) {
        const float* Ag = g_h + (size_t)(t & 1) * (BB * HH) + (size_t)b0 * HH;
        float* Hout = g_h + (size_t)((t + 1) & 1) * (BB * HH);

        if (tid < BT) {
            toksm[tid] = tok_is_32 ? inp32[t * BB + b0 + tid]
                                   : (int)inp64[(size_t)t * BB + b0 + tid];
        }

        float acc[2][4][4];
#pragma unroll
        for (int mb = 0; mb < 2; mb++)
#pragma unroll
            for (int nb = 0; nb < 4; nb++)
#pragma unroll
                for (int e = 0; e < 4; e++) acc[mb][nb][e] = 0.f;

        // A chunk 0 -> B0, commit group {W0, A0}; chunk 1 -> B1, commit
#pragma unroll
        for (int i = 0; i < 8; i++) cpa16(bufb[0] + a_dst[i], Ag + a_src[i]);
        CP_COMMIT();
#pragma unroll
        for (int i = 0; i < 8; i++) cpa16(bufb[1] + a_dst[i], Ag + a_src[i] + KC);
#pragma unroll
        for (int i = 0; i < 4; i++) cpa16(bufb[1] + w_dst[i], g_w + w_src[i] + KC);
        CP_COMMIT();

        // mainloop: wait(k) -> bar -> issue(k+2) -> mma(k)
        int cur = 0, nxt2 = 2;
#pragma unroll 1
        for (int kc = 0; kc < NKC; kc++) {
            if (kc < NKC - 1) cp_wait<1>(); else cp_wait<0>();
            __syncthreads();
            if (kc + 2 < NKC) {
                const int koff = (kc + 2) * KC;
                const unsigned nb_ = bufb[nxt2];
#pragma unroll
                for (int i = 0; i < 8; i++) cpa16(nb_ + a_dst[i], Ag + a_src[i] + koff);
#pragma unroll
                for (int i = 0; i < 4; i++) cpa16(nb_ + w_dst[i], g_w + w_src[i] + koff);
                CP_COMMIT();
            }
            const float* As = sm + (OFF_B0 + cur * STAGE_FLOATS);
            mma_chunk(As, As + BT * AS_STRIDE, acc, warp_m, warp_n, lane);
            cur = (cur == 2) ? 0 : cur + 1;
            nxt2 = (nxt2 == 2) ? 0 : nxt2 + 1;
        }
        __syncthreads();   // all warps done mma(15) before B0 is reused below

        // issue next step's W0 into B0 (uncommitted; commits with next A0)
        const bool last = (t == TT - 1);
        if (!last) {
#pragma unroll
            for (int i = 0; i < 4; i++) cpa16(bufb[0] + w_dst[i], g_w + w_src[i]);
        }

        // ---- register epilogue: gates -> LSTM cell -> h, no smem roundtrip ----
        {
            const int u0 = unit0 + warp_n * 8 + (lt << 1);
            const int pc = warp_n * 32 + (lt << 1);   // base P col for gate 0
#pragma unroll
            for (int mb = 0; mb < 2; mb++) {
                int r0 = warp_m * 32 + mb * 16 + lg;
                int v0 = toksm[r0], v1 = toksm[r0 + 8];
                // gate g lives at acc[mb][g][rh*2+e]; P col = pc + g*8 + e
                float gv4[4][4];
#pragma unroll
                for (int g = 0; g < 4; g++) {
                    const float* P0 = Psm + v0 * PS + pc + g * 8;
                    const float* P1 = Psm + v1 * PS + pc + g * 8;
                    gv4[g][0] = acc[mb][g][0] + P0[0];
                    gv4[g][1] = acc[mb][g][1] + P0[1];
                    gv4[g][2] = acc[mb][g][2] + P1[0];
                    gv4[g][3] = acc[mb][g][3] + P1[1];
                }
#pragma unroll
                for (int rh = 0; rh < 2; rh++) {
                    float hv[2];
#pragma unroll
                    for (int e = 0; e < 2; e++) {
                        int ix = rh * 2 + e;
                        float iv = fsig(gv4[0][ix]);
                        float fv = fsig(gv4[1][ix]);
                        float gg = ftanh(gv4[2][ix]);
                        float ov = fsig(gv4[3][ix]);
                        float cn = fv * creg[mb * 4 + ix] + iv * gg;
                        float hn = ov * ftanh(cn);
                        creg[mb * 4 + ix] = cn;
                        hv[e] = last ? hn : tf32r(hn);
                    }
                    int r = r0 + rh * 8;
                    *(float2*)(Hout + (size_t)(b0 + r) * HH + u0) = make_float2(hv[0], hv[1]);
                }
            }
        }
        grid_sync();
    }

    // ---- output head: h_last (fp32) in buffer 0 ----
    if (tid < 128) {
        int id = cid * 128 + tid;            // 128 CTAs x 128 = 16384 = 256*64
        int b = id >> 6, o = id & 63;
        const float4* hr = (const float4*)(g_h + (size_t)b * HH);
        const float4* wr = (const float4*)(w_out + (size_t)o * HH);
        float s = 0.f;
#pragma unroll 8
        for (int k = 0; k < HH / 4; k++) {
            float4 a = __ldcg(hr + k);
            float4 w = wr[k];
            s += a.x * w.x + a.y * w.y + a.z * w.z + a.w * w.w;
        }
        out[id] = s + b_out[o];
    }
}

extern "C" void kernel_launch(void* const* d_in, const int* in_sizes, int n_in,
                              void* d_out, int out_size) {
    (void)in_sizes; (void)n_in; (void)out_size;
    const size_t smem_bytes = (size_t)SMEM_FLOATS * sizeof(float);
    cudaFuncSetAttribute(lstm_persistent_kernel,
                         cudaFuncAttributeMaxDynamicSharedMemorySize, (int)smem_bytes);
    lstm_persistent_kernel<<<NCTA, NTHR, smem_bytes>>>(
        (const void*)d_in[0],
        (const float*)d_in[1],
        (const float*)d_in[2],
        (const float*)d_in[3],
        (const float*)d_in[4],
        (const float*)d_in[5],
        (const float*)d_in[6],
        (const float*)d_in[7],
        (const float*)d_in[8],
        (const float*)d_in[9],
        (float*)d_out);
}

// round 12
// speedup vs baseline: 1.7404x; 1.0205x over previous
#include <cuda_runtime.h>
#include <cstdint>

// Problem dims
#define TT 128
#define BB 256
#define II 512
#define HH 1024
#define VV 128
#define OO 64
#define NG 4096   // 4*H

// Decomposition (champion shape)
#define NCTA 128        // 2 batch-blocks x 64 unit-blocks
#define BT 128          // batch rows per CTA (M)
#define UT 16           // hidden units per CTA
#define CT 64           // gate cols per CTA (N)
#define KC 64           // K chunk
#define NKC (HH/KC)     // 16
#define NTHR 256        // 8 warps: 4x2 warp grid, 32x32 tile per warp

#define AS_STRIDE 68
#define STAGE_FLOATS ((BT + CT) * AS_STRIDE)   // 13056

#define PS 65           // P table row stride

// smem float offsets
#define OFF_P   0                         // 128*65 = 8320 floats
#define OFF_TOK 8320                      // 136 ints
#define OFF_B0  8456
#define OFF_B1  (OFF_B0 + STAGE_FLOATS)   // 21512
#define OFF_B2  (OFF_B1 + STAGE_FLOATS)   // 34568
#define SMEM_FLOATS (OFF_B2 + STAGE_FLOATS)   // 190496 B

// ---- static scratch ----
__device__ float g_h[2*BB*HH];        // ping-pong hidden state (tf32; fp32 last step)
__device__ float g_w[NG*HH];          // tf32-pre-rounded w_hh
__device__ unsigned g_cnt;
__device__ unsigned g_rel;

__device__ __forceinline__ float tf32r(float x) {
    unsigned v; asm("cvt.rna.tf32.f32 %0, %1;" : "=r"(v) : "f"(x));
    return __uint_as_float(v);
}
__device__ __forceinline__ unsigned ld_acq(const unsigned* p) {
    unsigned v; asm volatile("ld.acquire.gpu.u32 %0, [%1];" : "=r"(v) : "l"(p) : "memory");
    return v;
}
__device__ __forceinline__ void grid_sync() {
    __syncthreads();
    if (threadIdx.x == 0) {
        unsigned r0 = ld_acq(&g_rel);
        __threadfence();
        unsigned old = atomicAdd(&g_cnt, 1u);
        if (old == (unsigned)(NCTA - 1)) {
            g_cnt = 0; __threadfence(); atomicAdd(&g_rel, 1u);
        } else {
            while (ld_acq(&g_rel) == r0) { }
        }
    }
    __syncthreads();
}

// col j -> gate=(j>>3)&3, unit=(j>>5)*8+(j&7): all 4 gates of a cell in one thread.
__device__ __forceinline__ int colIdx(int j, int unit0) {
    return (((j >> 3) & 3) << 10) + unit0 + ((j >> 5) << 3) + (j & 7);
}

__device__ __forceinline__ void mma8(float d[4], const unsigned a[4],
                                     unsigned b0, unsigned b1) {
    asm volatile(
        "mma.sync.aligned.m16n8k8.row.col.f32.tf32.tf32.f32 "
        "{%0,%1,%2,%3}, {%4,%5,%6,%7}, {%8,%9}, {%0,%1,%2,%3};\n"
        : "+f"(d[0]), "+f"(d[1]), "+f"(d[2]), "+f"(d[3])
        : "r"(a[0]), "r"(a[1]), "r"(a[2]), "r"(a[3]), "r"(b0), "r"(b1));
}
__device__ __forceinline__ void ldsm4(unsigned addr, unsigned& r0, unsigned& r1,
                                      unsigned& r2, unsigned& r3) {
    asm volatile("ldmatrix.sync.aligned.m8n8.x4.shared.b16 {%0,%1,%2,%3}, [%4];"
                 : "=r"(r0), "=r"(r1), "=r"(r2), "=r"(r3) : "r"(addr));
}
__device__ __forceinline__ void cpa16(unsigned dst, const float* src) {
    asm volatile("cp.async.cg.shared.global [%0], [%1], 16;" :: "r"(dst), "l"(src));
}
#define CP_COMMIT() asm volatile("cp.async.commit_group;" ::: "memory")
template<int N> __device__ __forceinline__ void cp_wait() {
    asm volatile("cp.async.wait_group %0;" :: "n"(N) : "memory");
}

// fast pointwise ops
__device__ __forceinline__ float fsig(float x) {
    return __fdividef(1.0f, 1.0f + __expf(-x));
}
__device__ __forceinline__ float ftanh(float x) {
    return 1.0f - 2.0f * __fdividef(1.0f, __expf(2.0f * x) + 1.0f);
}

// Synchronous tile load with tf32 rounding (P-table phase only).
__device__ __forceinline__ void load_tiles_cvt(
    float* As, float* Ws,
    const float* __restrict__ A, int lda,
    const float* __restrict__ W, int ldw,
    int kc, int unit0, int tid)
{
#pragma unroll
    for (int i = 0; i < 8; i++) {
        int id = tid + NTHR * i;
        int r = id >> 4, q = id & 15;
        float4 v = __ldcg((const float4*)(A + (size_t)r * lda + kc + q * 4));
        v.x = tf32r(v.x); v.y = tf32r(v.y); v.z = tf32r(v.z); v.w = tf32r(v.w);
        *(float4*)(As + r * AS_STRIDE + q * 4) = v;
    }
#pragma unroll
    for (int i = 0; i < 4; i++) {
        int id = tid + NTHR * i;
        int r = id >> 4, q = id & 15;
        float4 v = __ldcg((const float4*)(W + (size_t)colIdx(r, unit0) * ldw + kc + q * 4));
        v.x = tf32r(v.x); v.y = tf32r(v.y); v.z = tf32r(v.z); v.w = tf32r(v.w);
        *(float4*)(Ws + r * AS_STRIDE + q * 4) = v;
    }
}

// ldmatrix-based chunk MMA. stg = smem byte address of stage base.
// a_lm[mb], b_lm[p] are per-lane ldmatrix byte offsets within the stage.
__device__ __forceinline__ void mma_chunk(
    unsigned stg, const unsigned a_lm[2], const unsigned b_lm[2],
    float acc[2][4][4])
{
#pragma unroll
    for (int kk = 0; kk < KC; kk += 8) {
        unsigned a[2][4], b[2][4];
        ldsm4(stg + a_lm[0] + kk * 4, a[0][0], a[0][1], a[0][2], a[0][3]);
        ldsm4(stg + a_lm[1] + kk * 4, a[1][0], a[1][1], a[1][2], a[1][3]);
        ldsm4(stg + b_lm[0] + kk * 4, b[0][0], b[0][1], b[0][2], b[0][3]);
        ldsm4(stg + b_lm[1] + kk * 4, b[1][0], b[1][1], b[1][2], b[1][3]);
#pragma unroll
        for (int mb = 0; mb < 2; mb++) {
            mma8(acc[mb][0], a[mb], b[0][0], b[0][1]);
            mma8(acc[mb][1], a[mb], b[0][2], b[0][3]);
            mma8(acc[mb][2], a[mb], b[1][0], b[1][1]);
            mma8(acc[mb][3], a[mb], b[1][2], b[1][3]);
        }
    }
}

__global__ void __launch_bounds__(NTHR, 1)
lstm_persistent_kernel(
    const void* __restrict__ inp_raw,
    const float* __restrict__ h0,
    const float* __restrict__ c0,
    const float* __restrict__ emb,
    const float* __restrict__ w_ih,
    const float* __restrict__ w_hh,
    const float* __restrict__ b_ih,
    const float* __restrict__ b_hh,
    const float* __restrict__ w_out,
    const float* __restrict__ b_out,
    float* __restrict__ out)
{
    extern __shared__ float sm[];
    float* Psm   = sm + OFF_P;
    int*   toksm = (int*)(sm + OFF_TOK);

    const int tid  = threadIdx.x;
    const int lane = tid & 31, wid = tid >> 5;
    const int warp_m = wid >> 1, warp_n = wid & 1;  // 4x2
    const int cid = blockIdx.x;
    const int bi = cid >> 6, hi = cid & 63;
    const int b0 = bi * BT;
    const int unit0 = hi * UT;
    const int lg = lane >> 2, lt = lane & 3;

    const unsigned sbase = (unsigned)__cvta_generic_to_shared(sm);
    const int* inp32 = (const int*)inp_raw;
    const long long* inp64 = (const long long*)inp_raw;

    // ---- token dtype detection ----
    if (tid == 0) toksm[128] = 0;
    __syncthreads();
    {
        int f = 0;
        for (int i = tid; i < 128; i += NTHR)
            if (inp32[2 * i + 1] != 0) f = 1;
        if (f) atomicOr(&toksm[128], 1);
    }

    // ---- init: tf32-round w_hh -> g_w; tf32-round h0 -> g_h buf0 ----
    {
        const float4* src = (const float4*)w_hh;
        float4* dst = (float4*)g_w;
        int base = cid * ((NG * HH / 4) / NCTA);
        for (int i = tid; i < (NG * HH / 4) / NCTA; i += NTHR) {
            float4 v = src[base + i];
            v.x = tf32r(v.x); v.y = tf32r(v.y); v.z = tf32r(v.z); v.w = tf32r(v.w);
            dst[base + i] = v;
        }
        const float4* hs = (const float4*)h0;
        float4* hd = (float4*)g_h;
        int hb = cid * ((BB * HH / 4) / NCTA);
        for (int i = tid; i < (BB * HH / 4) / NCTA; i += NTHR) {
            float4 v = hs[hb + i];
            v.x = tf32r(v.x); v.y = tf32r(v.y); v.z = tf32r(v.z); v.w = tf32r(v.w);
            hd[hb + i] = v;
        }
    }

    // ---- c state in registers ----
    float creg[8];
    {
        const int u0 = unit0 + warp_n * 8 + (lt << 1);
#pragma unroll
        for (int mb = 0; mb < 2; mb++)
#pragma unroll
            for (int rh = 0; rh < 2; rh++) {
                int r = warp_m * 32 + mb * 16 + rh * 8 + lg;
                const float2 cv = *(const float2*)(c0 + (size_t)(b0 + r) * HH + u0);
                creg[mb * 4 + rh * 2 + 0] = cv.x;
                creg[mb * 4 + rh * 2 + 1] = cv.y;
            }
    }
    grid_sync();
    const int tok_is_32 = toksm[128];

    // ---- per-thread cp.async address precompute ----
    int a_src[8];  unsigned a_dst[8];
    int w_src[4];  unsigned w_dst[4];
#pragma unroll
    for (int i = 0; i < 8; i++) {
        int id = tid + NTHR * i;
        int r = id >> 4, q = id & 15;
        a_src[i] = r * HH + q * 4;
        a_dst[i] = (unsigned)((r * AS_STRIDE + q * 4) * 4);
    }
#pragma unroll
    for (int i = 0; i < 4; i++) {
        int id = tid + NTHR * i;
        int r = id >> 4, q = id & 15;
        w_src[i] = colIdx(r, unit0) * HH + q * 4;
        w_dst[i] = (unsigned)(((BT * AS_STRIDE) + r * AS_STRIDE + q * 4) * 4);
    }
    const unsigned bufb[3] = { sbase + OFF_B0 * 4, sbase + OFF_B1 * 4, sbase + OFF_B2 * 4 };

    // ---- per-lane ldmatrix offsets (bytes within a stage) ----
    // A fragment (m16k8): m0 rows r0..7/col kk, m1 rows+8/col kk, m2 rows/col kk+4, m3 rows+8/col kk+4
    unsigned a_lm[2], b_lm[2];
#pragma unroll
    for (int mb = 0; mb < 2; mb++) {
        int row = warp_m * 32 + mb * 16 + (lane & 7) + (((lane >> 3) & 1) << 3);
        int col = (lane >> 4) << 2;
        a_lm[mb] = (unsigned)((row * AS_STRIDE + col) * 4);
    }
    // B fragments for nb pair (2p, 2p+1): m0 rows cn..7/col kk, m1 rows/col kk+4,
    // m2 rows+8/col kk, m3 rows+8/col kk+4
#pragma unroll
    for (int p = 0; p < 2; p++) {
        int row = warp_n * 32 + p * 16 + (lane & 7) + ((lane >> 4) << 3);
        int col = ((lane >> 3) & 1) << 2;
        b_lm[p] = (unsigned)(((BT * AS_STRIDE) + row * AS_STRIDE + col) * 4);
    }

    // ---- P table: P[v][j] = emb[v] . w_ih[col(j)] + b_ih + b_hh ----
    {
        float* As = sm + OFF_B0;
        float* Ws = As + BT * AS_STRIDE;
        float acc[2][4][4];
#pragma unroll
        for (int mb = 0; mb < 2; mb++)
#pragma unroll
            for (int nb = 0; nb < 4; nb++)
#pragma unroll
                for (int e = 0; e < 4; e++) acc[mb][nb][e] = 0.f;

        for (int kc = 0; kc < II; kc += KC) {
            __syncthreads();
            load_tiles_cvt(As, Ws, emb, II, w_ih, II, kc, unit0, tid);
            __syncthreads();
            mma_chunk(bufb[0], a_lm, b_lm, acc);
        }
        __syncthreads();
#pragma unroll
        for (int mb = 0; mb < 2; mb++) {
            int r0 = warp_m * 32 + mb * 16 + lg;
#pragma unroll
            for (int nb = 0; nb < 4; nb++) {
                int c0c = warp_n * 32 + nb * 8 + (lt << 1);
                int gc0 = colIdx(c0c, unit0), gc1 = colIdx(c0c + 1, unit0);
                float bias0 = b_ih[gc0] + b_hh[gc0];
                float bias1 = b_ih[gc1] + b_hh[gc1];
                Psm[r0 * PS + c0c]           = acc[mb][nb][0] + bias0;
                Psm[r0 * PS + c0c + 1]       = acc[mb][nb][1] + bias1;
                Psm[(r0 + 8) * PS + c0c]     = acc[mb][nb][2] + bias0;
                Psm[(r0 + 8) * PS + c0c + 1] = acc[mb][nb][3] + bias1;
            }
        }
        __syncthreads();
    }

    // ---- issue W chunk 0 for step 0 (uncommitted; commits with A0) ----
#pragma unroll
    for (int i = 0; i < 4; i++) cpa16(bufb[0] + w_dst[i], g_w + w_src[i]);

    // ---- recurrence: 3-stage pipeline, ldmatrix fragments, register epilogue ----
    for (int t = 0; t < TT; t++) {
        const float* Ag = g_h + (size_t)(t & 1) * (BB * HH) + (size_t)b0 * HH;
        float* Hout = g_h + (size_t)((t + 1) & 1) * (BB * HH);

        if (tid < BT) {
            toksm[tid] = tok_is_32 ? inp32[t * BB + b0 + tid]
                                   : (int)inp64[(size_t)t * BB + b0 + tid];
        }

        float acc[2][4][4];
#pragma unroll
        for (int mb = 0; mb < 2; mb++)
#pragma unroll
            for (int nb = 0; nb < 4; nb++)
#pragma unroll
                for (int e = 0; e < 4; e++) acc[mb][nb][e] = 0.f;

        // A chunk 0 -> B0, commit group {W0, A0}; chunk 1 -> B1, commit
#pragma unroll
        for (int i = 0; i < 8; i++) cpa16(bufb[0] + a_dst[i], Ag + a_src[i]);
        CP_COMMIT();
#pragma unroll
        for (int i = 0; i < 8; i++) cpa16(bufb[1] + a_dst[i], Ag + a_src[i] + KC);
#pragma unroll
        for (int i = 0; i < 4; i++) cpa16(bufb[1] + w_dst[i], g_w + w_src[i] + KC);
        CP_COMMIT();

        // mainloop: wait(k) -> bar -> issue(k+2) -> mma(k)
        int cur = 0, nxt2 = 2;
#pragma unroll 1
        for (int kc = 0; kc < NKC; kc++) {
            if (kc < NKC - 1) cp_wait<1>(); else cp_wait<0>();
            __syncthreads();
            if (kc + 2 < NKC) {
                const int koff = (kc + 2) * KC;
                const unsigned nb_ = bufb[nxt2];
#pragma unroll
                for (int i = 0; i < 8; i++) cpa16(nb_ + a_dst[i], Ag + a_src[i] + koff);
#pragma unroll
                for (int i = 0; i < 4; i++) cpa16(nb_ + w_dst[i], g_w + w_src[i] + koff);
                CP_COMMIT();
            }
            mma_chunk(bufb[cur], a_lm, b_lm, acc);
            cur = (cur == 2) ? 0 : cur + 1;
            nxt2 = (nxt2 == 2) ? 0 : nxt2 + 1;
        }
        __syncthreads();   // all warps done mma(15) before B0 reuse

        const bool last = (t == TT - 1);
        if (!last) {
#pragma unroll
            for (int i = 0; i < 4; i++) cpa16(bufb[0] + w_dst[i], g_w + w_src[i]);
        }

        // ---- register epilogue ----
        {
            const int u0 = unit0 + warp_n * 8 + (lt << 1);
            const int pc = warp_n * 32 + (lt << 1);
#pragma unroll
            for (int mb = 0; mb < 2; mb++) {
                int r0 = warp_m * 32 + mb * 16 + lg;
                int v0 = toksm[r0], v1 = toksm[r0 + 8];
                float gv4[4][4];
#pragma unroll
                for (int g = 0; g < 4; g++) {
                    const float* P0 = Psm + v0 * PS + pc + g * 8;
                    const float* P1 = Psm + v1 * PS + pc + g * 8;
                    gv4[g][0] = acc[mb][g][0] + P0[0];
                    gv4[g][1] = acc[mb][g][1] + P0[1];
                    gv4[g][2] = acc[mb][g][2] + P1[0];
                    gv4[g][3] = acc[mb][g][3] + P1[1];
                }
#pragma unroll
                for (int rh = 0; rh < 2; rh++) {
                    float hv[2];
#pragma unroll
                    for (int e = 0; e < 2; e++) {
                        int ix = rh * 2 + e;
                        float iv = fsig(gv4[0][ix]);
                        float fv = fsig(gv4[1][ix]);
                        float gg = ftanh(gv4[2][ix]);
                        float ov = fsig(gv4[3][ix]);
                        float cn = fv * creg[mb * 4 + ix] + iv * gg;
                        float hn = ov * ftanh(cn);
                        creg[mb * 4 + ix] = cn;
                        hv[e] = last ? hn : tf32r(hn);
                    }
                    int r = r0 + rh * 8;
                    *(float2*)(Hout + (size_t)(b0 + r) * HH + u0) = make_float2(hv[0], hv[1]);
                }
            }
        }
        grid_sync();
    }

    // ---- output head: h_last (fp32) in buffer 0 ----
    if (tid < 128) {
        int id = cid * 128 + tid;
        int b = id >> 6, o = id & 63;
        const float4* hr = (const float4*)(g_h + (size_t)b * HH);
        const float4* wr = (const float4*)(w_out + (size_t)o * HH);
        float s = 0.f;
#pragma unroll 8
        for (int k = 0; k < HH / 4; k++) {
            float4 a = __ldcg(hr + k);
            float4 w = wr[k];
            s += a.x * w.x + a.y * w.y + a.z * w.z + a.w * w.w;
        }
        out[id] = s + b_out[o];
    }
}

extern "C" void kernel_launch(void* const* d_in, const int* in_sizes, int n_in,
                              void* d_out, int out_size) {
    (void)in_sizes; (void)n_in; (void)out_size;
    const size_t smem_bytes = (size_t)SMEM_FLOATS * sizeof(float);
    cudaFuncSetAttribute(lstm_persistent_kernel,
                         cudaFuncAttributeMaxDynamicSharedMemorySize, (int)smem_bytes);
    lstm_persistent_kernel<<<NCTA, NTHR, smem_bytes>>>(
        (const void*)d_in[0],
        (const float*)d_in[1],
        (const float*)d_in[2],
        (const float*)d_in[3],
        (const float*)d_in[4],
        (const float*)d_in[5],
        (const float*)d_in[6],
        (const float*)d_in[7],
        (const float*)d_in[8],
        (const float*)d_in[9],
        (float*)d_out);
}